// round 2
// baseline (speedup 1.0000x reference)
#include <cuda_runtime.h>

// 2-layer LSTM (PyTorch convention) + linear head + clip, B=256 T=2048 I=32 H=64.
// One CTA (256 threads) handles 2 batch elements for all 2048 timesteps.
// Thread j owns gate row r(j) = (j%4)*64 + j/4 for both layers, so the 4 gates
// of hidden unit h = j/4 live in adjacent lanes -> cell update via warp shuffle,
// cell state c stays in registers. Layer-1 weights (96) + 32 of layer-2 in regs,
// remaining 96 layer-2 weights in smem (row stride 100 floats: conflict-free
// LDS.128, since 100 mod 32 == 4 -> one phase covers all 32 banks).

#define TT 2048
#define NI 32
#define NH 64
#define W2STRIDE 100

__device__ __forceinline__ float sigmf(float v) {
    return __fdividef(1.f, 1.f + __expf(-v));
}
__device__ __forceinline__ float tanhfast(float v) {
    return __fdividef(2.f, 1.f + __expf(-2.f * v)) - 1.f;
}
__device__ __forceinline__ float lstm_cell(float gi, float gf, float gg, float go, float& c) {
    float i = sigmf(gi);
    float f = sigmf(gf);
    float g = tanhfast(gg);
    float o = sigmf(go);
    c = fmaf(f, c, i * g);
    return o * tanhfast(c);
}

__global__ void __launch_bounds__(256, 1)
lstm2_kernel(const float* __restrict__ x,
             const float* __restrict__ Wih0, const float* __restrict__ Whh0,
             const float* __restrict__ bih0, const float* __restrict__ bhh0,
             const float* __restrict__ Wih1, const float* __restrict__ Whh1,
             const float* __restrict__ bih1, const float* __restrict__ bhh1,
             const float* __restrict__ Wout, const float* __restrict__ bOut,
             float* __restrict__ out)
{
    extern __shared__ float sm[];
    float* W2s  = sm;                       // 256 * 100 floats (per-row layer-2 weights)
    float* v1   = sm + 256 * W2STRIDE;      // [2][96]  : x_t(32) | h1_{t-1}(64)
    float* v2   = v1 + 192;                 // [2][128] : h1_t(64) | h2_{t-1}(64)
    float* ybuf = v2 + 256;                 // [2][8] per-warp y partials

    const int tid  = threadIdx.x;
    const int lane = tid & 31;
    const int wrp  = tid >> 5;
    const int r    = ((tid & 3) << 6) | (tid >> 2);   // permuted gate row
    const int h    = tid >> 2;                        // hidden index for this quad
    const int bb   = blockIdx.x << 1;                 // base batch

    const float bias1 = bih0[r] + bhh0[r];
    const float bias2 = bih1[r] + bhh1[r];
    const float wo    = ((tid & 3) == 0) ? Wout[h] : 0.f;
    const float bo    = bOut[0];

    // ---- load weights: layer-1 row (96) + first 32 of layer-2 row into regs ----
    float w1[96];
    {
        const float4* A = (const float4*)Wih0;   // [256][32]
        #pragma unroll
        for (int k = 0; k < 8; k++) {
            float4 v = A[r * 8 + k];
            w1[4*k+0] = v.x; w1[4*k+1] = v.y; w1[4*k+2] = v.z; w1[4*k+3] = v.w;
        }
        const float4* Bm = (const float4*)Whh0;  // [256][64]
        #pragma unroll
        for (int k = 0; k < 16; k++) {
            float4 v = Bm[r * 16 + k];
            w1[32+4*k+0] = v.x; w1[32+4*k+1] = v.y; w1[32+4*k+2] = v.z; w1[32+4*k+3] = v.w;
        }
    }
    float w2[32];
    {
        const float4* A = (const float4*)Wih1;   // [256][64]
        #pragma unroll
        for (int k = 0; k < 8; k++) {
            float4 v = A[r * 16 + k];
            w2[4*k+0] = v.x; w2[4*k+1] = v.y; w2[4*k+2] = v.z; w2[4*k+3] = v.w;
        }
        // smem part of layer-2 row: k=0..31 <- Wih1[r][32..63], k=32..95 <- Whh1[r][0..63]
        float* rw = W2s + tid * W2STRIDE;
        #pragma unroll
        for (int k = 0; k < 8; k++)
            *(float4*)(rw + 4*k) = A[r * 16 + 8 + k];
        const float4* Bm = (const float4*)Whh1;  // [256][64]
        #pragma unroll
        for (int k = 0; k < 16; k++)
            *(float4*)(rw + 32 + 4*k) = Bm[r * 16 + k];
    }

    // zero v1/v2/ybuf
    for (int i = tid; i < 192 + 256 + 16; i += 256) v1[i] = 0.f;
    __syncthreads();

    // initial x_0 into v1 x-slots
    if (tid < 16) {
        int g = tid >> 3;
        float4 xv = *(const float4*)(x + (size_t)(bb + g) * TT * NI + (tid & 7) * 4);
        *(float4*)(v1 + g * 96 + (tid & 7) * 4) = xv;
    }
    __syncthreads();

    float c10 = 0.f, c11 = 0.f, c20 = 0.f, c21 = 0.f;
    const float* rw = W2s + tid * W2STRIDE;
    const unsigned FULL = 0xffffffffu;
    const int base = lane & ~3;

    for (int t = 0; t < TT; ++t) {
        // prefetch x_{t+1} (hidden under layer-1 compute)
        float4 xr = make_float4(0.f, 0.f, 0.f, 0.f);
        const bool ldx = (tid < 16) && (t + 1 < TT);
        if (ldx) {
            int g = tid >> 3;
            xr = *(const float4*)(x + ((size_t)(bb + g) * TT + (t + 1)) * NI + (tid & 7) * 4);
        }

        // ---- layer-1 gate pre-activations (register weights, broadcast v1) ----
        float acc0 = bias1, acc1 = bias1;
        #pragma unroll
        for (int c = 0; c < 24; ++c) {
            float4 va = *(const float4*)(v1 + 4 * c);
            float4 vb = *(const float4*)(v1 + 96 + 4 * c);
            acc0 = fmaf(w1[4*c+0], va.x, acc0);
            acc0 = fmaf(w1[4*c+1], va.y, acc0);
            acc0 = fmaf(w1[4*c+2], va.z, acc0);
            acc0 = fmaf(w1[4*c+3], va.w, acc0);
            acc1 = fmaf(w1[4*c+0], vb.x, acc1);
            acc1 = fmaf(w1[4*c+1], vb.y, acc1);
            acc1 = fmaf(w1[4*c+2], vb.z, acc1);
            acc1 = fmaf(w1[4*c+3], vb.w, acc1);
        }
        // gather 4 gates of this quad and run the cell (all lanes redundantly)
        float gi0 = __shfl_sync(FULL, acc0, base + 0);
        float gf0 = __shfl_sync(FULL, acc0, base + 1);
        float gg0 = __shfl_sync(FULL, acc0, base + 2);
        float go0 = __shfl_sync(FULL, acc0, base + 3);
        float gi1 = __shfl_sync(FULL, acc1, base + 0);
        float gf1 = __shfl_sync(FULL, acc1, base + 1);
        float gg1 = __shfl_sync(FULL, acc1, base + 2);
        float go1 = __shfl_sync(FULL, acc1, base + 3);
        float h10 = lstm_cell(gi0, gf0, gg0, go0, c10);
        float h11 = lstm_cell(gi1, gf1, gg1, go1, c11);

        __syncthreads();   // S1: everyone done reading v1 (and prior v2 h1-part use)

        if ((tid & 3) == 0) {
            v1[32 + h]       = h10;  v1[96 + 32 + h]  = h11;
            v2[h]            = h10;  v2[128 + h]      = h11;
        }
        if (ldx) {
            int g = tid >> 3;
            *(float4*)(v1 + g * 96 + (tid & 7) * 4) = xr;
        }
        if (tid < 2 && t > 0) {      // finalize y_{t-1} (off critical path)
            float s = bo;
            #pragma unroll
            for (int k = 0; k < 8; k++) s += ybuf[tid * 8 + k];
            out[(size_t)(bb + tid) * TT + (t - 1)] = fminf(fmaxf(s, 0.f), 1.f);
        }

        __syncthreads();   // S2: h1_t / x_{t+1} visible

        // ---- layer-2 gate pre-activations ----
        float A0 = bias2, A1 = bias2;
        #pragma unroll
        for (int c = 0; c < 8; ++c) {            // register part: v2[0..31] (h1)
            float4 va = *(const float4*)(v2 + 4 * c);
            float4 vb = *(const float4*)(v2 + 128 + 4 * c);
            A0 = fmaf(w2[4*c+0], va.x, A0);
            A0 = fmaf(w2[4*c+1], va.y, A0);
            A0 = fmaf(w2[4*c+2], va.z, A0);
            A0 = fmaf(w2[4*c+3], va.w, A0);
            A1 = fmaf(w2[4*c+0], vb.x, A1);
            A1 = fmaf(w2[4*c+1], vb.y, A1);
            A1 = fmaf(w2[4*c+2], vb.z, A1);
            A1 = fmaf(w2[4*c+3], vb.w, A1);
        }
        #pragma unroll
        for (int c = 0; c < 24; ++c) {           // smem part: v2[32..127]
            float4 wv = *(const float4*)(rw + 4 * c);
            float4 va = *(const float4*)(v2 + 32 + 4 * c);
            float4 vb = *(const float4*)(v2 + 160 + 4 * c);
            A0 = fmaf(wv.x, va.x, A0);
            A0 = fmaf(wv.y, va.y, A0);
            A0 = fmaf(wv.z, va.z, A0);
            A0 = fmaf(wv.w, va.w, A0);
            A1 = fmaf(wv.x, vb.x, A1);
            A1 = fmaf(wv.y, vb.y, A1);
            A1 = fmaf(wv.z, vb.z, A1);
            A1 = fmaf(wv.w, vb.w, A1);
        }
        float Gi0 = __shfl_sync(FULL, A0, base + 0);
        float Gf0 = __shfl_sync(FULL, A0, base + 1);
        float Gg0 = __shfl_sync(FULL, A0, base + 2);
        float Go0 = __shfl_sync(FULL, A0, base + 3);
        float Gi1 = __shfl_sync(FULL, A1, base + 0);
        float Gf1 = __shfl_sync(FULL, A1, base + 1);
        float Gg1 = __shfl_sync(FULL, A1, base + 2);
        float Go1 = __shfl_sync(FULL, A1, base + 3);
        float h20 = lstm_cell(Gi0, Gf0, Gg0, Go0, c20);
        float h21 = lstm_cell(Gi1, Gf1, Gg1, Go1, c21);

        __syncthreads();   // S3: everyone done reading v2 (h2_{t-1})

        if ((tid & 3) == 0) { v2[64 + h] = h20; v2[192 + h] = h21; }

        // y head partials: non-base lanes have wo == 0
        float p0 = h20 * wo;
        float p1 = h21 * wo;
        #pragma unroll
        for (int off = 16; off; off >>= 1) {
            p0 += __shfl_xor_sync(FULL, p0, off);
            p1 += __shfl_xor_sync(FULL, p1, off);
        }
        if (lane == 0) { ybuf[wrp] = p0; ybuf[8 + wrp] = p1; }
    }

    __syncthreads();
    if (tid < 2) {   // finalize y_{T-1}
        float s = bo;
        #pragma unroll
        for (int k = 0; k < 8; k++) s += ybuf[tid * 8 + k];
        out[(size_t)(bb + tid) * TT + (TT - 1)] = fminf(fmaxf(s, 0.f), 1.f);
    }
}

extern "C" void kernel_launch(void* const* d_in, const int* in_sizes, int n_in,
                              void* d_out, int out_size)
{
    (void)in_sizes; (void)n_in; (void)out_size;
    const float* x    = (const float*)d_in[0];
    const float* Wih0 = (const float*)d_in[1];
    const float* Whh0 = (const float*)d_in[2];
    const float* bih0 = (const float*)d_in[3];
    const float* bhh0 = (const float*)d_in[4];
    const float* Wih1 = (const float*)d_in[5];
    const float* Whh1 = (const float*)d_in[6];
    const float* bih1 = (const float*)d_in[7];
    const float* bhh1 = (const float*)d_in[8];
    const float* Wout = (const float*)d_in[9];
    const float* bOut = (const float*)d_in[10];
    float* out = (float*)d_out;

    const int smem = (256 * W2STRIDE + 192 + 256 + 16) * (int)sizeof(float);
    cudaFuncSetAttribute(lstm2_kernel, cudaFuncAttributeMaxDynamicSharedMemorySize, smem);
    lstm2_kernel<<<128, 256, smem>>>(x, Wih0, Whh0, bih0, bhh0,
                                     Wih1, Whh1, bih1, bhh1, Wout, bOut, out);
}

// round 3
// speedup vs baseline: 1.2474x; 1.2474x over previous
#include <cuda_runtime.h>

// 2-layer LSTM + linear head + clip. B=256 T=2048 I=32 H=64.
// One CTA (256 thr) = 2 batch elements, persistent over all 2048 steps.
// Thread j owns gate row r = (j%4)*64 + j/4; quad of lanes = 4 gates of one
// hidden unit -> cell via warp shuffle, c state in registers.
// Math uses packed fma.rn.f32x2 with column-pairing: weight pack = (w[2k],w[2k+1])
// straight from row-major global memory; activation pack = (v[2k],v[2k+1]) as
// ulonglong2 smem loads. Layer-1 weights (48 packs) + 48 of 64 layer-2 packs in
// registers; last 16 layer-2 packs per thread in smem at 144B stride
// (conflict-free LDS.128: lane delta 36 words -> banks 4i mod 32).

#define TT 2048
#define NI 32
#define RWSTR 18   // per-thread smem weight stride, in ull (18*8 = 144 B)

typedef unsigned long long ull;

__device__ __forceinline__ float sigmf(float v) {
    return __fdividef(1.f, 1.f + __expf(-v));
}
__device__ __forceinline__ void fma2(ull& d, ull a, ull b) {
    asm("fma.rn.f32x2 %0, %1, %2, %0;" : "+l"(d) : "l"(a), "l"(b));
}
__device__ __forceinline__ ull add2(ull a, ull b) {
    ull r; asm("add.rn.f32x2 %0, %1, %2;" : "=l"(r) : "l"(a), "l"(b)); return r;
}
__device__ __forceinline__ float2 unpk(ull v) {
    float2 r; asm("mov.b64 {%0, %1}, %2;" : "=f"(r.x), "=f"(r.y) : "l"(v)); return r;
}
__device__ __forceinline__ ull pk(float a, float b) {
    ull r; asm("mov.b64 %0, {%1, %2};" : "=l"(r) : "f"(a), "f"(b)); return r;
}
// gates already activated: gi,gf,go = sigmoid, gg = tanh
__device__ __forceinline__ float cell_rest(float gi, float gf, float gg, float go, float& c) {
    c = fmaf(gf, c, gi * gg);
    return go * fmaf(2.f, sigmf(2.f * c), -1.f);   // o * tanh(c)
}

__global__ void __launch_bounds__(256, 1)
lstm2_kernel(const float* __restrict__ x,
             const float* __restrict__ Wih0, const float* __restrict__ Whh0,
             const float* __restrict__ bih0, const float* __restrict__ bhh0,
             const float* __restrict__ Wih1, const float* __restrict__ Whh1,
             const float* __restrict__ bih1, const float* __restrict__ bhh1,
             const float* __restrict__ Wout, const float* __restrict__ bOut,
             float* __restrict__ out)
{
    extern __shared__ ull smu[];
    // [0 .. 256*RWSTR)            per-thread layer-2 weight packs (16 used of 18)
    // then float regions:
    float* v1   = (float*)(smu + 256 * RWSTR);  // [2][96]  : x_t(32) | h1_{t-1}(64)
    float* v2   = v1 + 192;                     // [2][128] : h1_t(64) | h2_{t-1}(64)
    float* ybuf = v2 + 256;                     // [2][8] per-warp y partials

    const int tid  = threadIdx.x;
    const int lane = tid & 31;
    const int wrp  = tid >> 5;
    const int q    = tid & 3;                          // gate: 0=i 1=f 2=g 3=o
    const int r    = (q << 6) | (tid >> 2);            // permuted gate row
    const int h    = tid >> 2;                         // hidden unit of this quad
    const int bb   = blockIdx.x << 1;                  // base batch

    const ull b1p = pk(bih0[r] + bhh0[r], 0.f);
    const ull b2p = pk(bih1[r] + bhh1[r], 0.f);
    const float wo = (q == 0) ? Wout[h] : 0.f;
    const float bo = bOut[0];
    // branch-free activation: act = msc * sigm(kml * A) + mad
    const float kml = (q == 2) ? 2.f : 1.f;
    const float msc = (q == 2) ? 2.f : 1.f;
    const float mad = (q == 2) ? -1.f : 0.f;

    // ---- weights: layer-1 (48 packs) + layer-2 first 48 packs into regs ----
    ull w1p[48];
    {
        const ulonglong2* A = (const ulonglong2*)(Wih0 + r * NI);   // 32 floats
        #pragma unroll
        for (int k = 0; k < 8; k++) { ulonglong2 v = A[k]; w1p[2*k] = v.x; w1p[2*k+1] = v.y; }
        const ulonglong2* B = (const ulonglong2*)(Whh0 + r * 64);   // 64 floats
        #pragma unroll
        for (int k = 0; k < 16; k++) { ulonglong2 v = B[k]; w1p[16+2*k] = v.x; w1p[17+2*k] = v.y; }
    }
    ull w2p[48];
    {
        const ulonglong2* A = (const ulonglong2*)(Wih1 + r * 64);   // h1 cols 0..63
        #pragma unroll
        for (int k = 0; k < 16; k++) { ulonglong2 v = A[k]; w2p[2*k] = v.x; w2p[2*k+1] = v.y; }
        const ulonglong2* B = (const ulonglong2*)(Whh1 + r * 64);   // h2 cols
        #pragma unroll
        for (int k = 0; k < 8; k++) { ulonglong2 v = B[k]; w2p[32+2*k] = v.x; w2p[33+2*k] = v.y; }
        // h2 cols 32..63 -> per-thread smem packs
        ulonglong2* RW = (ulonglong2*)(smu + tid * RWSTR);
        #pragma unroll
        for (int k = 0; k < 8; k++) RW[k] = B[8 + k];
    }

    // zero v1/v2/ybuf
    for (int i = tid; i < 192 + 256 + 16; i += 256) v1[i] = 0.f;
    __syncthreads();

    // initial x_0
    if (tid < 16) {
        int g = tid >> 3;
        float4 xv = *(const float4*)(x + (size_t)(bb + g) * TT * NI + (tid & 7) * 4);
        *(float4*)(v1 + g * 96 + (tid & 7) * 4) = xv;
    }
    __syncthreads();

    float c10 = 0.f, c11 = 0.f, c20 = 0.f, c21 = 0.f;
    const ulonglong2* RW = (const ulonglong2*)(smu + tid * RWSTR);
    const unsigned FULL = 0xffffffffu;
    const int base = lane & ~3;

    for (int t = 0; t < TT; ++t) {
        // prefetch x_{t+1}
        float4 xr = make_float4(0.f, 0.f, 0.f, 0.f);
        const bool ldx = (tid < 16) && (t + 1 < TT);
        if (ldx) {
            int g = tid >> 3;
            xr = *(const float4*)(x + ((size_t)(bb + g) * TT + (t + 1)) * NI + (tid & 7) * 4);
        }

        // ---- layer-1 pre-activations: packed column pairs ----
        ull a0A = b1p, a0B = 0ull, a1A = b1p, a1B = 0ull;
        {
            const ulonglong2* Va = (const ulonglong2*)v1;
            const ulonglong2* Vb = (const ulonglong2*)(v1 + 96);
            #pragma unroll
            for (int c = 0; c < 24; ++c) {
                ulonglong2 va = Va[c], vb = Vb[c];
                fma2(a0A, w1p[2*c],   va.x);
                fma2(a0B, w1p[2*c+1], va.y);
                fma2(a1A, w1p[2*c],   vb.x);
                fma2(a1B, w1p[2*c+1], vb.y);
            }
        }
        float2 s0 = unpk(add2(a0A, a0B));
        float2 s1 = unpk(add2(a1A, a1B));
        float A0 = s0.x + s0.y;
        float A1 = s1.x + s1.y;
        // own-gate activation, then gather activated gates
        float act0 = fmaf(msc, sigmf(kml * A0), mad);
        float act1 = fmaf(msc, sigmf(kml * A1), mad);
        float gi0 = __shfl_sync(FULL, act0, base + 0);
        float gf0 = __shfl_sync(FULL, act0, base + 1);
        float gg0 = __shfl_sync(FULL, act0, base + 2);
        float go0 = __shfl_sync(FULL, act0, base + 3);
        float gi1 = __shfl_sync(FULL, act1, base + 0);
        float gf1 = __shfl_sync(FULL, act1, base + 1);
        float gg1 = __shfl_sync(FULL, act1, base + 2);
        float go1 = __shfl_sync(FULL, act1, base + 3);
        float h10 = cell_rest(gi0, gf0, gg0, go0, c10);
        float h11 = cell_rest(gi1, gf1, gg1, go1, c11);

        __syncthreads();   // S1: all reads of v1 (and prior v2) done

        if (q == 0) {
            v1[32 + h]      = h10;  v1[96 + 32 + h] = h11;
            v2[h]           = h10;  v2[128 + h]     = h11;
        }
        if (ldx) {
            int g = tid >> 3;
            *(float4*)(v1 + g * 96 + (tid & 7) * 4) = xr;
        }
        if (tid < 2 && t > 0) {       // finalize y_{t-1} off critical path
            float s = bo;
            #pragma unroll
            for (int k = 0; k < 8; k++) s += ybuf[tid * 8 + k];
            out[(size_t)(bb + tid) * TT + (t - 1)] = fminf(fmaxf(s, 0.f), 1.f);
        }

        __syncthreads();   // S2: h1_t / x_{t+1} published

        // ---- layer-2 pre-activations ----
        ull b0A = b2p, b0B = 0ull, b1A = b2p, b1B = 0ull;
        {
            const ulonglong2* U0 = (const ulonglong2*)v2;
            const ulonglong2* U1 = (const ulonglong2*)(v2 + 128);
            #pragma unroll
            for (int c = 0; c < 24; ++c) {        // cols 0..95 (reg packs)
                ulonglong2 ua = U0[c], ub = U1[c];
                fma2(b0A, w2p[2*c],   ua.x);
                fma2(b0B, w2p[2*c+1], ua.y);
                fma2(b1A, w2p[2*c],   ub.x);
                fma2(b1B, w2p[2*c+1], ub.y);
            }
            #pragma unroll
            for (int c = 0; c < 8; ++c) {         // cols 96..127 (smem packs)
                ulonglong2 wv = RW[c];
                ulonglong2 ua = U0[24 + c], ub = U1[24 + c];
                fma2(b0A, wv.x, ua.x);
                fma2(b0B, wv.y, ua.y);
                fma2(b1A, wv.x, ub.x);
                fma2(b1B, wv.y, ub.y);
            }
        }
        float2 u0 = unpk(add2(b0A, b0B));
        float2 u1 = unpk(add2(b1A, b1B));
        float B0 = u0.x + u0.y;
        float B1 = u1.x + u1.y;
        float bact0 = fmaf(msc, sigmf(kml * B0), mad);
        float bact1 = fmaf(msc, sigmf(kml * B1), mad);
        float Gi0 = __shfl_sync(FULL, bact0, base + 0);
        float Gf0 = __shfl_sync(FULL, bact0, base + 1);
        float Gg0 = __shfl_sync(FULL, bact0, base + 2);
        float Go0 = __shfl_sync(FULL, bact0, base + 3);
        float Gi1 = __shfl_sync(FULL, bact1, base + 0);
        float Gf1 = __shfl_sync(FULL, bact1, base + 1);
        float Gg1 = __shfl_sync(FULL, bact1, base + 2);
        float Go1 = __shfl_sync(FULL, bact1, base + 3);
        float h20 = cell_rest(Gi0, Gf0, Gg0, Go0, c20);
        float h21 = cell_rest(Gi1, Gf1, Gg1, Go1, c21);

        __syncthreads();   // S3: all reads of v2 (h2_{t-1}) done

        if (q == 0) { v2[64 + h] = h20; v2[192 + h] = h21; }

        // y head partials (wo == 0 on non-base lanes; h2 valid on all lanes)
        float p0 = h20 * wo;
        float p1 = h21 * wo;
        #pragma unroll
        for (int off = 16; off; off >>= 1) {
            p0 += __shfl_xor_sync(FULL, p0, off);
            p1 += __shfl_xor_sync(FULL, p1, off);
        }
        if (lane == 0) { ybuf[wrp] = p0; ybuf[8 + wrp] = p1; }
    }

    __syncthreads();
    if (tid < 2) {   // finalize y_{T-1}
        float s = bo;
        #pragma unroll
        for (int k = 0; k < 8; k++) s += ybuf[tid * 8 + k];
        out[(size_t)(bb + tid) * TT + (TT - 1)] = fminf(fmaxf(s, 0.f), 1.f);
    }
}

extern "C" void kernel_launch(void* const* d_in, const int* in_sizes, int n_in,
                              void* d_out, int out_size)
{
    (void)in_sizes; (void)n_in; (void)out_size;
    const float* x    = (const float*)d_in[0];
    const float* Wih0 = (const float*)d_in[1];
    const float* Whh0 = (const float*)d_in[2];
    const float* bih0 = (const float*)d_in[3];
    const float* bhh0 = (const float*)d_in[4];
    const float* Wih1 = (const float*)d_in[5];
    const float* Whh1 = (const float*)d_in[6];
    const float* bih1 = (const float*)d_in[7];
    const float* bhh1 = (const float*)d_in[8];
    const float* Wout = (const float*)d_in[9];
    const float* bOut = (const float*)d_in[10];
    float* out = (float*)d_out;

    const int smem = 256 * RWSTR * (int)sizeof(ull) + (192 + 256 + 16) * (int)sizeof(float);
    cudaFuncSetAttribute(lstm2_kernel, cudaFuncAttributeMaxDynamicSharedMemorySize, smem);
    lstm2_kernel<<<128, 256, smem>>>(x, Wih0, Whh0, bih0, bhh0,
                                     Wih1, Whh1, bih1, bhh1, Wout, bOut, out);
}